// round 16
// baseline (speedup 1.0000x reference)
#include <cuda_runtime.h>
#include <cuda_fp16.h>
#include <cstdint>

#define NN    50000
#define EE    640000
#define DINN  128
#define DH    256
#define DOUTK 128
#define MT    3128          // padded m-tiles (16 rows each)
#define NTILE 3125          // NN/16 exactly

// ===================== scratch =============================================
__device__ int   g_deg[NN];
__device__ float g_invc[NN];
__device__ int   g_rowstart[NN + 1];
__device__ int   g_cursor[NN];
__device__ int   g_csr[EE];
__device__ __align__(256) float g_T[(size_t)NN * DH];
__device__ __align__(256) float g_S[(size_t)NN * DH];

// fp16 row-major copies (gather reads + LN2 skip)
__device__ __align__(256) __half gXh[(size_t)NN * DINN];
__device__ __align__(256) __half gHhalf[(size_t)NN * DH];
__device__ __align__(256) __half gYh[(size_t)NN * DOUTK];

// fragment-tiled fp16 A operands: per (mtile,kstep,lane): one uint4 (4 regs)
__device__ __align__(256) uint4 gP1[(size_t)MT * 16 * 32];
__device__ __align__(256) uint4 gP2[(size_t)MT * 16 * 32];

// fragment-tiled fp16 B: per (ntile,kstep,lane): one uint2 (2 regs)
__device__ __align__(256) uint2 gB1[32 * 16 * 32];
__device__ __align__(256) uint2 gBsk[32 * 8 * 32];
__device__ __align__(256) uint2 gB2[32 * 32 * 32];
__device__ __align__(256) uint2 gB3[32 * 16 * 32];

__device__ __forceinline__ uint32_t pack_h2(float f0, float f1) {
  __half2 h = __floats2half2_rn(f0, f1);
  return *(uint32_t*)&h;
}

// scatter one k-pair of row r (0..15) into an SMEM fragment block (fp16)
__device__ __forceinline__ void smem_afrag(uint32_t* sf, int p, int r,
                                           uint32_t w) {
  const int kstep = p >> 3, pp = p & 7;
  const int L = ((r & 7) << 2) | (pp & 3);
  const int reg = (r >> 3) + ((pp >> 2) << 1);
  sf[(kstep * 32 + L) * 4 + reg] = w;
}

// ===================== CSR build ===========================================
__global__ void count_kernel(const int* __restrict__ dst) {
  int e = blockIdx.x * blockDim.x + threadIdx.x;
  if (e < EE) atomicAdd(&g_deg[dst[e]], 1);
}
__global__ void scan_kernel() {
  constexpr int T = 1024;
  constexpr int CHUNK = (NN + T - 1) / T;
  __shared__ int sums[T];
  const int tid = threadIdx.x;
  const int start = tid * CHUNK;
  const int end = (start + CHUNK < NN) ? (start + CHUNK) : NN;
  int s = 0;
  for (int i = start; i < end; ++i) s += g_deg[i];
  sums[tid] = s;
  __syncthreads();
  for (int off = 1; off < T; off <<= 1) {
    int v = 0;
    if (tid >= off) v = sums[tid - off];
    __syncthreads();
    if (tid >= off) sums[tid] += v;
    __syncthreads();
  }
  int run = (tid == 0) ? 0 : sums[tid - 1];
  for (int i = start; i < end; ++i) {
    const int d = g_deg[i];
    g_rowstart[i] = run;
    g_cursor[i]   = run;
    g_invc[i]     = 1.0f / (float)(d > 1 ? d : 1);
    run += d;
  }
  if (end == NN) g_rowstart[NN] = run;
}
__global__ void fill_kernel(const int* __restrict__ src, const int* __restrict__ dst) {
  int e = blockIdx.x * blockDim.x + threadIdx.x;
  if (e < EE) {
    int pos = atomicAdd(&g_cursor[dst[e]], 1);
    g_csr[pos] = src[e];
  }
}

// ===================== pack x (fragments nk=8 + fp16 row copy + zero deg) ==
__global__ void __launch_bounds__(512)
pack_x_kernel(const float* __restrict__ x) {
  __shared__ uint32_t sf[1024];          // nk=8 fp16 fragment block (4KB)
  const int mtile = blockIdx.x;
  const int tid = threadIdx.x;
  const int z = blockIdx.x * 512 + tid;
  if (z < NN) g_deg[z] = 0;
#pragma unroll
  for (int it = tid; it < 1024; it += 512) {
    const int r = it >> 6, p = it & 63;
    const int row = mtile * 16 + r;
    float2 v = *(const float2*)(x + (size_t)row * DINN + 2 * p);
    const uint32_t w = pack_h2(v.x, v.y);
    smem_afrag(sf, p, r, w);
    *(uint32_t*)(gXh + (size_t)row * DINN + 2 * p) = w;
  }
  __syncthreads();
  if (tid < 256) {
    uint4* dst = gP2 + (size_t)mtile * 256;   // nk=8: 256 uint4 per mtile
    dst[tid] = ((const uint4*)sf)[tid];
  }
}

// ===================== merged weight prep (fp16 B fragments) ===============
__device__ __forceinline__ void prep_one(const float* __restrict__ W, int N,
                                         int Kp, uint32_t* dst, int nk,
                                         int pOff, int nOff, int li) {
  const int n = li / Kp, p = li % Kp;
  const float f0 = W[(size_t)(2 * p) * N + n];
  const float f1 = W[(size_t)(2 * p + 1) * N + n];
  const uint32_t w = pack_h2(f0, f1);
  const int ng = nOff + n, pg = pOff + p;
  const int kstep = pg >> 3, pp = pg & 7;
  const int L = ((ng & 7) << 2) | (pp & 3);
  const int reg = pp >> 2;
  dst[((size_t)((ng >> 3) * nk + kstep) * 32 + L) * 2 + reg] = w;
}
__global__ void prep_all(const float* W1l, const float* W1r, const float* Wsk,
                         const float* W2l, const float* W2r, const float* W3l,
                         const float* W3r) {
  int idx = blockIdx.x * blockDim.x + threadIdx.x;
  if (idx < 16384)        prep_one(W1l, 256, 64,  (uint32_t*)gB1,  16, 0,   0,   idx);
  else if (idx < 32768)   prep_one(W1r, 256, 64,  (uint32_t*)gB1,  16, 64,  0,   idx - 16384);
  else if (idx < 49152)   prep_one(Wsk, 256, 64,  (uint32_t*)gBsk, 8,  0,   0,   idx - 32768);
  else if (idx < 81920)   prep_one(W2l, 256, 128, (uint32_t*)gB2,  32, 0,   0,   idx - 49152);
  else if (idx < 114688)  prep_one(W2r, 256, 128, (uint32_t*)gB2,  32, 128, 0,   idx - 81920);
  else if (idx < 131072)  prep_one(W3l, 128, 128, (uint32_t*)gB3,  16, 0,   0,   idx - 114688);
  else if (idx < 147456)  prep_one(W3r, 128, 128, (uint32_t*)gB3,  16, 0,   128, idx - 131072);
}

// ===================== aggregation kernels (mtile CTAs) ====================
// layer-1: mean over gXh (fp16, D=128), warp/node, smem-staged -> gP1 (nk=8)
__global__ void __launch_bounds__(512) agg_x_kernel() {
  __shared__ uint32_t sf[1024];
  const int mtile = blockIdx.x;
  const int wid = threadIdx.x >> 5, lane = threadIdx.x & 31;
  const int node = mtile * 16 + wid;
  const uint2* __restrict__ X = (const uint2*)gXh;
  float4 acc = make_float4(0.f, 0.f, 0.f, 0.f);
  const int beg = g_rowstart[node];
  const int end = g_rowstart[node + 1];
  int i = beg;
  for (; i + 8 <= end; i += 8) {
    uint2 u[8];
#pragma unroll
    for (int j = 0; j < 8; ++j) u[j] = X[(size_t)g_csr[i + j] * 32 + lane];
#pragma unroll
    for (int j = 0; j < 8; ++j) {
      float2 a = __half22float2(*(const __half2*)&u[j].x);
      float2 b = __half22float2(*(const __half2*)&u[j].y);
      acc.x += a.x; acc.y += a.y; acc.z += b.x; acc.w += b.y;
    }
  }
  for (; i < end; ++i) {
    uint2 u = X[(size_t)g_csr[i] * 32 + lane];
    float2 a = __half22float2(*(const __half2*)&u.x);
    float2 b = __half22float2(*(const __half2*)&u.y);
    acc.x += a.x; acc.y += a.y; acc.z += b.x; acc.w += b.y;
  }
  const float ic = g_invc[node];
  smem_afrag(sf, 2 * lane, wid, pack_h2(acc.x * ic, acc.y * ic));
  smem_afrag(sf, 2 * lane + 1, wid, pack_h2(acc.z * ic, acc.w * ic));
  __syncthreads();
  if (threadIdx.x < 256) {
    uint4* dst = gP1 + (size_t)mtile * 256;
    dst[threadIdx.x] = ((const uint4*)sf)[threadIdx.x];
  }
}

// layer-2: mean over gHhalf (fp16, D=256), warp/node, smem-staged -> gP1 (nk=16)
__global__ void __launch_bounds__(512) agg_h_kernel() {
  __shared__ uint32_t sf[2048];
  const int mtile = blockIdx.x;
  const int wid = threadIdx.x >> 5, lane = threadIdx.x & 31;
  const int node = mtile * 16 + wid;
  const uint4* __restrict__ X = (const uint4*)gHhalf;
  float acc[8];
#pragma unroll
  for (int j = 0; j < 8; ++j) acc[j] = 0.f;
  const int beg = g_rowstart[node];
  const int end = g_rowstart[node + 1];
  int i = beg;
  for (; i + 4 <= end; i += 4) {
    uint4 u[4];
#pragma unroll
    for (int j = 0; j < 4; ++j) u[j] = X[(size_t)g_csr[i + j] * 32 + lane];
#pragma unroll
    for (int j = 0; j < 4; ++j) {
      float2 a = __half22float2(*(const __half2*)&u[j].x);
      float2 b = __half22float2(*(const __half2*)&u[j].y);
      float2 c = __half22float2(*(const __half2*)&u[j].z);
      float2 d = __half22float2(*(const __half2*)&u[j].w);
      acc[0] += a.x; acc[1] += a.y; acc[2] += b.x; acc[3] += b.y;
      acc[4] += c.x; acc[5] += c.y; acc[6] += d.x; acc[7] += d.y;
    }
  }
  for (; i < end; ++i) {
    uint4 u = X[(size_t)g_csr[i] * 32 + lane];
    float2 a = __half22float2(*(const __half2*)&u.x);
    float2 b = __half22float2(*(const __half2*)&u.y);
    float2 c = __half22float2(*(const __half2*)&u.z);
    float2 d = __half22float2(*(const __half2*)&u.w);
    acc[0] += a.x; acc[1] += a.y; acc[2] += b.x; acc[3] += b.y;
    acc[4] += c.x; acc[5] += c.y; acc[6] += d.x; acc[7] += d.y;
  }
  const float ic = g_invc[node];
#pragma unroll
  for (int j = 0; j < 4; ++j)
    smem_afrag(sf, 4 * lane + j, wid, pack_h2(acc[2 * j] * ic, acc[2 * j + 1] * ic));
  __syncthreads();
  uint4* dst = gP1 + (size_t)mtile * 512;     // nk=16: 512 uint4 per mtile
  dst[threadIdx.x] = ((const uint4*)sf)[threadIdx.x];
}

// final layer: out = mean_agg(Yh) + Z + b3l
__global__ void agg_final_kernel(const float* __restrict__ b3l,
                                 float* __restrict__ out) {
  const int warp = (blockIdx.x * blockDim.x + threadIdx.x) >> 5;
  if (warp >= NN) return;
  const int lane = threadIdx.x & 31;
  const uint2* __restrict__ Y = (const uint2*)gYh;
  float4 acc = make_float4(0.f, 0.f, 0.f, 0.f);
  const int beg = g_rowstart[warp];
  const int end = g_rowstart[warp + 1];
  int i = beg;
  for (; i + 8 <= end; i += 8) {
    uint2 u[8];
#pragma unroll
    for (int j = 0; j < 8; ++j) u[j] = Y[(size_t)g_csr[i + j] * 32 + lane];
#pragma unroll
    for (int j = 0; j < 8; ++j) {
      float2 a = __half22float2(*(const __half2*)&u[j].x);
      float2 b = __half22float2(*(const __half2*)&u[j].y);
      acc.x += a.x; acc.y += a.y; acc.z += b.x; acc.w += b.y;
    }
  }
  for (; i < end; ++i) {
    uint2 u = Y[(size_t)g_csr[i] * 32 + lane];
    float2 a = __half22float2(*(const __half2*)&u.x);
    float2 b = __half22float2(*(const __half2*)&u.y);
    acc.x += a.x; acc.y += a.y; acc.z += b.x; acc.w += b.y;
  }
  const float ic = g_invc[warp];
  float4 z = *(const float4*)(g_T + (size_t)warp * DH + 128 + lane * 4);
  float4 b = *(const float4*)(b3l + lane * 4);
  float4 r;
  r.x = acc.x * ic + z.x + b.x;
  r.y = acc.y * ic + z.y + b.y;
  r.z = acc.z * ic + z.z + b.z;
  r.w = acc.w * ic + z.w + b.w;
  *(float4*)(out + (size_t)warp * DOUTK + lane * 4) = r;
}

// ===================== fragment-tiled fp16 MMA GEMM ========================
// CTA 64(M) x 128(N); 8 warps = 2M x 4N; warp tile 32x32.
// A fragments prefetched TWO ksteps ahead (3 buffers, covers L2 latency);
// B loaded in-loop (L1-resident). 3 CTAs/SM occupancy.
__device__ __forceinline__ void mma_f16(float* d, const uint32_t* a,
                                        const uint32_t* b) {
  asm volatile(
      "mma.sync.aligned.m16n8k16.row.col.f32.f16.f16.f32 "
      "{%0,%1,%2,%3}, {%4,%5,%6,%7}, {%8,%9}, {%0,%1,%2,%3};"
      : "+f"(d[0]), "+f"(d[1]), "+f"(d[2]), "+f"(d[3])
      : "r"(a[0]), "r"(a[1]), "r"(a[2]), "r"(a[3]), "r"(b[0]), "r"(b[1]));
}

__global__ void __launch_bounds__(256, 3)
gemm_mma(int a1id, int nk1, int nk2, int bid, int nkB,
         const float* __restrict__ bias, int cid, int storeYh) {
  const int tid = threadIdx.x;
  const int wid = tid >> 5;
  const int lane = tid & 31;
  const int warpM = wid & 1;
  const int warpN = wid >> 1;
  const int rowTile = blockIdx.x * 64;
  const int colTile = blockIdx.y * 128;

  const uint4* __restrict__ A1 = (a1id == 1) ? gP1 : gP2;
  const uint4* __restrict__ A2 = gP2;
  const uint2* __restrict__ Bf =
      (bid == 1) ? gB1 : (bid == 2) ? gBsk : (bid == 3) ? gB2 : gB3;

  int mtile[2];
#pragma unroll
  for (int mt = 0; mt < 2; ++mt) mtile[mt] = blockIdx.x * 4 + warpM * 2 + mt;

  const uint2* bBase = Bf + ((size_t)(blockIdx.y * 16 + warpN * 4) * nkB) * 32 + lane;

  float acc[2][4][4];
#pragma unroll
  for (int mt = 0; mt < 2; ++mt)
#pragma unroll
    for (int nt = 0; nt < 4; ++nt)
#pragma unroll
      for (int r = 0; r < 4; ++r) acc[mt][nt][r] = 0.f;

  const int nks = nk1 + nk2;

  uint4 aB[3][2];     // 3-deep A prefetch ring
  auto ldA = [&](int ks, int buf) {
#pragma unroll
    for (int mt = 0; mt < 2; ++mt) {
      if (ks < nk1) aB[buf][mt] = A1[((size_t)mtile[mt] * nk1 + ks) * 32 + lane];
      else          aB[buf][mt] = A2[((size_t)mtile[mt] * nk2 + (ks - nk1)) * 32 + lane];
    }
  };

  ldA(0, 0);
  if (nks > 1) ldA(1, 1);
#pragma unroll 3
  for (int ks = 0; ks < nks; ++ks) {
    const int buf = ks % 3;
    if (ks + 2 < nks) ldA(ks + 2, (ks + 2) % 3);

    uint2 bB[4];
#pragma unroll
    for (int nt = 0; nt < 4; ++nt) bB[nt] = bBase[(size_t)nt * nkB * 32 + ks * 32];

#pragma unroll
    for (int mt = 0; mt < 2; ++mt)
#pragma unroll
      for (int nt = 0; nt < 4; ++nt)
        mma_f16(acc[mt][nt], (const uint32_t*)&aB[buf][mt],
                (const uint32_t*)&bB[nt]);
  }

  float* __restrict__ C = (cid == 1) ? g_T : g_S;
  const int doYh = storeYh && (blockIdx.y == 0);
  const int r0base = rowTile + warpM * 32 + (lane >> 2);
  const int cbase = colTile + warpN * 32 + (lane & 3) * 2;
#pragma unroll
  for (int mt = 0; mt < 2; ++mt) {
    const int rr = r0base + mt * 16;
#pragma unroll
    for (int nt = 0; nt < 4; ++nt) {
      const int col = cbase + nt * 8;
      float2 bv = make_float2(0.f, 0.f);
      if (bias) bv = *(const float2*)(bias + col);
      if (rr < NN) {
        float2 v = make_float2(acc[mt][nt][0] + bv.x, acc[mt][nt][1] + bv.y);
        *(float2*)(C + (size_t)rr * 256 + col) = v;
        if (doYh) *(__half2*)(gYh + (size_t)rr * DOUTK + col) = __floats2half2_rn(v.x, v.y);
      }
      if (rr + 8 < NN) {
        float2 v = make_float2(acc[mt][nt][2] + bv.x, acc[mt][nt][3] + bv.y);
        *(float2*)(C + (size_t)(rr + 8) * 256 + col) = v;
        if (doYh) *(__half2*)(gYh + (size_t)(rr + 8) * DOUTK + col) = __floats2half2_rn(v.x, v.y);
      }
    }
  }
}

// ===================== LayerNorm + ReLU + skip (mtile CTA) =================
// layer==1: skip=g_S (fp32); writes gHhalf (fp16 rows) + gP2 frags (nk=16)
// layer==2: skip=gHhalf (fp16); writes gP2 frags only
__global__ void __launch_bounds__(512)
ln_kernel(const float* __restrict__ gamma, const float* __restrict__ beta,
          int layer) {
  __shared__ uint32_t sf[2048];
  const int mtile = blockIdx.x;
  const int wid = threadIdx.x >> 5, lane = threadIdx.x & 31;
  const int row = mtile * 16 + wid;
  const float4* t4 = (const float4*)(g_T + (size_t)row * DH);
  float4 v0 = t4[lane];
  float4 v1 = t4[lane + 32];
  float sum = v0.x + v0.y + v0.z + v0.w + v1.x + v1.y + v1.z + v1.w;
  float sq = v0.x * v0.x + v0.y * v0.y + v0.z * v0.z + v0.w * v0.w +
             v1.x * v1.x + v1.y * v1.y + v1.z * v1.z + v1.w * v1.w;
#pragma unroll
  for (int off = 16; off > 0; off >>= 1) {
    sum += __shfl_xor_sync(0xffffffffu, sum, off);
    sq  += __shfl_xor_sync(0xffffffffu, sq, off);
  }
  const float mu = sum * (1.0f / DH);
  const float var = sq * (1.0f / DH) - mu * mu;
  const float rs = rsqrtf(var + 1e-5f);

  float4 sv0, sv1;
  if (layer == 1) {
    const float4* s4 = (const float4*)(g_S + (size_t)row * DH);
    sv0 = s4[lane];
    sv1 = s4[lane + 32];
  } else {
    uint2 h0 = ((const uint2*)gHhalf)[(size_t)row * 64 + lane];
    uint2 h1 = ((const uint2*)gHhalf)[(size_t)row * 64 + lane + 32];
    float2 a = __half22float2(*(const __half2*)&h0.x);
    float2 b = __half22float2(*(const __half2*)&h0.y);
    sv0 = make_float4(a.x, a.y, b.x, b.y);
    a = __half22float2(*(const __half2*)&h1.x);
    b = __half22float2(*(const __half2*)&h1.y);
    sv1 = make_float4(a.x, a.y, b.x, b.y);
  }
  const float4* g4 = (const float4*)gamma;
  const float4* b4 = (const float4*)beta;
#pragma unroll
  for (int v = 0; v < 2; ++v) {
    float4 tv = (v == 0) ? v0 : v1;
    float4 sv = (v == 0) ? sv0 : sv1;
    float4 gv = g4[lane + 32 * v];
    float4 bv = b4[lane + 32 * v];
    float4 r;
    r.x = fmaxf(0.f, (tv.x - mu) * rs * gv.x + bv.x) + sv.x;
    r.y = fmaxf(0.f, (tv.y - mu) * rs * gv.y + bv.y) + sv.y;
    r.z = fmaxf(0.f, (tv.z - mu) * rs * gv.z + bv.z) + sv.z;
    r.w = fmaxf(0.f, (tv.w - mu) * rs * gv.w + bv.w) + sv.w;
    const uint32_t w0 = pack_h2(r.x, r.y);
    const uint32_t w1 = pack_h2(r.z, r.w);
    const int col = lane + 32 * v;
    if (layer == 1) {
      uint2 hh = make_uint2(w0, w1);
      ((uint2*)gHhalf)[(size_t)row * 64 + col] = hh;
    }
    smem_afrag(sf, 2 * col, wid, w0);
    smem_afrag(sf, 2 * col + 1, wid, w1);
  }
  __syncthreads();
  uint4* dst = gP2 + (size_t)mtile * 512;     // nk=16: 512 uint4 per mtile
  dst[threadIdx.x] = ((const uint4*)sf)[threadIdx.x];
}

// ===================== launch ==============================================
extern "C" void kernel_launch(void* const* d_in, const int* in_sizes, int n_in,
                              void* d_out, int out_size) {
  const float* x   = (const float*)d_in[0];
  const int*   ei  = (const int*)d_in[1];
  const float* W1l = (const float*)d_in[2];
  const float* b1l = (const float*)d_in[3];
  const float* W1r = (const float*)d_in[4];
  const float* g1  = (const float*)d_in[5];
  const float* be1 = (const float*)d_in[6];
  const float* Wsk = (const float*)d_in[7];
  const float* bsk = (const float*)d_in[8];
  const float* W2l = (const float*)d_in[9];
  const float* b2l = (const float*)d_in[10];
  const float* W2r = (const float*)d_in[11];
  const float* g2  = (const float*)d_in[12];
  const float* be2 = (const float*)d_in[13];
  const float* W3l = (const float*)d_in[14];
  const float* b3l = (const float*)d_in[15];
  const float* W3r = (const float*)d_in[16];
  float* out = (float*)d_out;

  const int* src = ei;
  const int* dst = ei + EE;

  const int edgeBlocks = (EE + 255) / 256;
  const int warpBlocks = (NN + 7) / 8;
  const dim3 gemmGrid((NN + 63) / 64, 2);

  // #1 pack_x(+zero_deg) ; #2 prep ; #3 count ; #4 GEMM (profiled slot)
  pack_x_kernel<<<NTILE, 512>>>(x);
  prep_all<<<(147456 + 255) / 256, 256>>>(W1l, W1r, Wsk, W2l, W2r, W3l, W3r);
  count_kernel<<<edgeBlocks, 256>>>(dst);
  gemm_mma<<<gemmGrid, 256>>>(2, 8, 0, 2, 8, bsk, 2, 0);   // S = x@Wsk + bsk

  scan_kernel<<<1, 1024>>>();
  fill_kernel<<<edgeBlocks, 256>>>(src, dst);

  // ---- layer 1: T = [agg(x)|x] @ [W1l;W1r] + b1l ; H = relu(LN(T)) + S
  agg_x_kernel<<<NTILE, 512>>>();
  gemm_mma<<<gemmGrid, 256>>>(1, 8, 8, 1, 16, b1l, 1, 0);
  ln_kernel<<<NTILE, 512>>>(g1, be1, 1);

  // ---- layer 2: T = [agg(H)|H] @ [W2l;W2r] + b2l ; H2 = relu(LN(T)) + H
  agg_h_kernel<<<NTILE, 512>>>();
  gemm_mma<<<gemmGrid, 256>>>(1, 16, 16, 3, 32, b2l, 1, 0);
  ln_kernel<<<NTILE, 512>>>(g2, be2, 2);

  // ---- layer 3: T = H2 @ [W3l|W3r] (Y also fp16) ;
  //      out = mean_agg(Yh) + T[:,128:] + b3l
  gemm_mma<<<gemmGrid, 256>>>(2, 16, 0, 4, 16, nullptr, 1, 1);
  agg_final_kernel<<<warpBlocks, 256>>>(b3l, out);
}

// round 17
// speedup vs baseline: 1.3198x; 1.3198x over previous
#include <cuda_runtime.h>
#include <cuda_fp16.h>
#include <cstdint>

#define NN    50000
#define EE    640000
#define DINN  128
#define DH    256
#define DOUTK 128
#define MT    3128          // padded m-tiles (16 rows each)
#define NTILE 3125          // NN/16 exactly

// ===================== scratch =============================================
__device__ int   g_deg[NN];
__device__ float g_invc[NN];
__device__ int   g_rowstart[NN + 1];
__device__ int   g_cursor[NN];
__device__ int   g_csr[EE];

// fp16 buffers: GEMM outputs T/S, row copies for gathers and LN2 skip
__device__ __align__(256) __half gThalf[(size_t)NN * DH];
__device__ __align__(256) __half gShalf[(size_t)NN * DH];
__device__ __align__(256) __half gXh[(size_t)NN * DINN];
__device__ __align__(256) __half gHhalf[(size_t)NN * DH];

// fragment-tiled fp16 A operands: per (mtile,kstep,lane): one uint4 (4 regs)
__device__ __align__(256) uint4 gP1[(size_t)MT * 16 * 32];
__device__ __align__(256) uint4 gP2[(size_t)MT * 16 * 32];

// fragment-tiled fp16 B: per (ntile,kstep,lane): one uint2 (2 regs)
__device__ __align__(256) uint2 gB1[32 * 16 * 32];
__device__ __align__(256) uint2 gBsk[32 * 8 * 32];
__device__ __align__(256) uint2 gB2[32 * 32 * 32];
__device__ __align__(256) uint2 gB3[32 * 16 * 32];

__device__ __forceinline__ uint32_t pack_h2(float f0, float f1) {
  __half2 h = __floats2half2_rn(f0, f1);
  return *(uint32_t*)&h;
}
// unpack uint2 (4 halfs) -> float4
__device__ __forceinline__ float4 unpack_u2(uint2 u) {
  float2 a = __half22float2(*(const __half2*)&u.x);
  float2 b = __half22float2(*(const __half2*)&u.y);
  return make_float4(a.x, a.y, b.x, b.y);
}

// scatter one k-pair of row r (0..15) into an SMEM fragment block (fp16)
__device__ __forceinline__ void smem_afrag(uint32_t* sf, int p, int r,
                                           uint32_t w) {
  const int kstep = p >> 3, pp = p & 7;
  const int L = ((r & 7) << 2) | (pp & 3);
  const int reg = (r >> 3) + ((pp >> 2) << 1);
  sf[(kstep * 32 + L) * 4 + reg] = w;
}

// ===================== CSR build ===========================================
__global__ void count_kernel(const int* __restrict__ dst) {
  int e = blockIdx.x * blockDim.x + threadIdx.x;
  if (e < EE) atomicAdd(&g_deg[dst[e]], 1);
}
__global__ void scan_kernel() {
  constexpr int T = 1024;
  constexpr int CHUNK = (NN + T - 1) / T;
  __shared__ int sums[T];
  const int tid = threadIdx.x;
  const int start = tid * CHUNK;
  const int end = (start + CHUNK < NN) ? (start + CHUNK) : NN;
  int s = 0;
  for (int i = start; i < end; ++i) s += g_deg[i];
  sums[tid] = s;
  __syncthreads();
  for (int off = 1; off < T; off <<= 1) {
    int v = 0;
    if (tid >= off) v = sums[tid - off];
    __syncthreads();
    if (tid >= off) sums[tid] += v;
    __syncthreads();
  }
  int run = (tid == 0) ? 0 : sums[tid - 1];
  for (int i = start; i < end; ++i) {
    const int d = g_deg[i];
    g_rowstart[i] = run;
    g_cursor[i]   = run;
    g_invc[i]     = 1.0f / (float)(d > 1 ? d : 1);
    run += d;
  }
  if (end == NN) g_rowstart[NN] = run;
}
__global__ void fill_kernel(const int* __restrict__ src, const int* __restrict__ dst) {
  int e = blockIdx.x * blockDim.x + threadIdx.x;
  if (e < EE) {
    int pos = atomicAdd(&g_cursor[dst[e]], 1);
    g_csr[pos] = src[e];
  }
}

// ===================== pack x (fragments nk=8 + fp16 row copy + zero deg) ==
__global__ void __launch_bounds__(512)
pack_x_kernel(const float* __restrict__ x) {
  __shared__ uint32_t sf[1024];          // nk=8 fp16 fragment block (4KB)
  const int mtile = blockIdx.x;
  const int tid = threadIdx.x;
  const int z = blockIdx.x * 512 + tid;
  if (z < NN) g_deg[z] = 0;
#pragma unroll
  for (int it = tid; it < 1024; it += 512) {
    const int r = it >> 6, p = it & 63;
    const int row = mtile * 16 + r;
    float2 v = *(const float2*)(x + (size_t)row * DINN + 2 * p);
    const uint32_t w = pack_h2(v.x, v.y);
    smem_afrag(sf, p, r, w);
    *(uint32_t*)(gXh + (size_t)row * DINN + 2 * p) = w;
  }
  __syncthreads();
  if (tid < 256) {
    uint4* dst = gP2 + (size_t)mtile * 256;   // nk=8: 256 uint4 per mtile
    dst[tid] = ((const uint4*)sf)[tid];
  }
}

// ===================== merged weight prep (fp16 B fragments) ===============
__device__ __forceinline__ void prep_one(const float* __restrict__ W, int N,
                                         int Kp, uint32_t* dst, int nk,
                                         int pOff, int nOff, int li) {
  const int n = li / Kp, p = li % Kp;
  const float f0 = W[(size_t)(2 * p) * N + n];
  const float f1 = W[(size_t)(2 * p + 1) * N + n];
  const uint32_t w = pack_h2(f0, f1);
  const int ng = nOff + n, pg = pOff + p;
  const int kstep = pg >> 3, pp = pg & 7;
  const int L = ((ng & 7) << 2) | (pp & 3);
  const int reg = pp >> 2;
  dst[((size_t)((ng >> 3) * nk + kstep) * 32 + L) * 2 + reg] = w;
}
__global__ void prep_all(const float* W1l, const float* W1r, const float* Wsk,
                         const float* W2l, const float* W2r, const float* W3l,
                         const float* W3r) {
  int idx = blockIdx.x * blockDim.x + threadIdx.x;
  if (idx < 16384)        prep_one(W1l, 256, 64,  (uint32_t*)gB1,  16, 0,   0,   idx);
  else if (idx < 32768)   prep_one(W1r, 256, 64,  (uint32_t*)gB1,  16, 64,  0,   idx - 16384);
  else if (idx < 49152)   prep_one(Wsk, 256, 64,  (uint32_t*)gBsk, 8,  0,   0,   idx - 32768);
  else if (idx < 81920)   prep_one(W2l, 256, 128, (uint32_t*)gB2,  32, 0,   0,   idx - 49152);
  else if (idx < 114688)  prep_one(W2r, 256, 128, (uint32_t*)gB2,  32, 128, 0,   idx - 81920);
  else if (idx < 131072)  prep_one(W3l, 128, 128, (uint32_t*)gB3,  16, 0,   0,   idx - 114688);
  else if (idx < 147456)  prep_one(W3r, 128, 128, (uint32_t*)gB3,  16, 0,   128, idx - 131072);
}

// ===================== aggregation kernels (mtile CTAs) ====================
// layer-1: mean over gXh (fp16, D=128), warp/node, smem-staged -> gP1 (nk=8)
__global__ void __launch_bounds__(512) agg_x_kernel() {
  __shared__ uint32_t sf[1024];
  const int mtile = blockIdx.x;
  const int wid = threadIdx.x >> 5, lane = threadIdx.x & 31;
  const int node = mtile * 16 + wid;
  const uint2* __restrict__ X = (const uint2*)gXh;
  float4 acc = make_float4(0.f, 0.f, 0.f, 0.f);
  const int beg = g_rowstart[node];
  const int end = g_rowstart[node + 1];
  int i = beg;
  for (; i + 8 <= end; i += 8) {
    uint2 u[8];
#pragma unroll
    for (int j = 0; j < 8; ++j) u[j] = X[(size_t)g_csr[i + j] * 32 + lane];
#pragma unroll
    for (int j = 0; j < 8; ++j) {
      float4 t = unpack_u2(u[j]);
      acc.x += t.x; acc.y += t.y; acc.z += t.z; acc.w += t.w;
    }
  }
  for (; i < end; ++i) {
    float4 t = unpack_u2(X[(size_t)g_csr[i] * 32 + lane]);
    acc.x += t.x; acc.y += t.y; acc.z += t.z; acc.w += t.w;
  }
  const float ic = g_invc[node];
  smem_afrag(sf, 2 * lane, wid, pack_h2(acc.x * ic, acc.y * ic));
  smem_afrag(sf, 2 * lane + 1, wid, pack_h2(acc.z * ic, acc.w * ic));
  __syncthreads();
  if (threadIdx.x < 256) {
    uint4* dst = gP1 + (size_t)mtile * 256;
    dst[threadIdx.x] = ((const uint4*)sf)[threadIdx.x];
  }
}

// layer-2: mean over gHhalf (fp16, D=256), warp/node, smem-staged -> gP1 (nk=16)
__global__ void __launch_bounds__(512) agg_h_kernel() {
  __shared__ uint32_t sf[2048];
  const int mtile = blockIdx.x;
  const int wid = threadIdx.x >> 5, lane = threadIdx.x & 31;
  const int node = mtile * 16 + wid;
  const uint4* __restrict__ X = (const uint4*)gHhalf;
  float acc[8];
#pragma unroll
  for (int j = 0; j < 8; ++j) acc[j] = 0.f;
  const int beg = g_rowstart[node];
  const int end = g_rowstart[node + 1];
  int i = beg;
  for (; i + 4 <= end; i += 4) {
    uint4 u[4];
#pragma unroll
    for (int j = 0; j < 4; ++j) u[j] = X[(size_t)g_csr[i + j] * 32 + lane];
#pragma unroll
    for (int j = 0; j < 4; ++j) {
      float4 t0 = unpack_u2(make_uint2(u[j].x, u[j].y));
      float4 t1 = unpack_u2(make_uint2(u[j].z, u[j].w));
      acc[0] += t0.x; acc[1] += t0.y; acc[2] += t0.z; acc[3] += t0.w;
      acc[4] += t1.x; acc[5] += t1.y; acc[6] += t1.z; acc[7] += t1.w;
    }
  }
  for (; i < end; ++i) {
    uint4 u = X[(size_t)g_csr[i] * 32 + lane];
    float4 t0 = unpack_u2(make_uint2(u.x, u.y));
    float4 t1 = unpack_u2(make_uint2(u.z, u.w));
    acc[0] += t0.x; acc[1] += t0.y; acc[2] += t0.z; acc[3] += t0.w;
    acc[4] += t1.x; acc[5] += t1.y; acc[6] += t1.z; acc[7] += t1.w;
  }
  const float ic = g_invc[node];
#pragma unroll
  for (int j = 0; j < 4; ++j)
    smem_afrag(sf, 4 * lane + j, wid, pack_h2(acc[2 * j] * ic, acc[2 * j + 1] * ic));
  __syncthreads();
  uint4* dst = gP1 + (size_t)mtile * 512;     // nk=16: 512 uint4 per mtile
  dst[threadIdx.x] = ((const uint4*)sf)[threadIdx.x];
}

// final layer: out = mean_agg(T[:,0:128]) + T[:,128:256] + b3l (T fp16)
__global__ void agg_final_kernel(const float* __restrict__ b3l,
                                 float* __restrict__ out) {
  const int warp = (blockIdx.x * blockDim.x + threadIdx.x) >> 5;
  if (warp >= NN) return;
  const int lane = threadIdx.x & 31;
  const uint2* __restrict__ T2 = (const uint2*)gThalf;  // 64 uint2 per row
  float4 acc = make_float4(0.f, 0.f, 0.f, 0.f);
  const int beg = g_rowstart[warp];
  const int end = g_rowstart[warp + 1];
  int i = beg;
  for (; i + 8 <= end; i += 8) {
    uint2 u[8];
#pragma unroll
    for (int j = 0; j < 8; ++j) u[j] = T2[(size_t)g_csr[i + j] * 64 + lane];
#pragma unroll
    for (int j = 0; j < 8; ++j) {
      float4 t = unpack_u2(u[j]);
      acc.x += t.x; acc.y += t.y; acc.z += t.z; acc.w += t.w;
    }
  }
  for (; i < end; ++i) {
    float4 t = unpack_u2(T2[(size_t)g_csr[i] * 64 + lane]);
    acc.x += t.x; acc.y += t.y; acc.z += t.z; acc.w += t.w;
  }
  const float ic = g_invc[warp];
  float4 z = unpack_u2(T2[(size_t)warp * 64 + 32 + lane]);
  float4 b = *(const float4*)(b3l + lane * 4);
  float4 r;
  r.x = acc.x * ic + z.x + b.x;
  r.y = acc.y * ic + z.y + b.y;
  r.z = acc.z * ic + z.z + b.z;
  r.w = acc.w * ic + z.w + b.w;
  *(float4*)(out + (size_t)warp * DOUTK + lane * 4) = r;
}

// ===================== fragment-tiled fp16 MMA GEMM (R13 config) ==========
// CTA 64(M) x 128(N); 8 warps = 2M x 4N; warp tile 32x32.
// A AND B fragments register-prefetched one kstep ahead; 3 CTAs/SM.
// Epilogue writes fp16 (gThalf / gShalf).
__device__ __forceinline__ void mma_f16(float* d, const uint32_t* a,
                                        const uint32_t* b) {
  asm volatile(
      "mma.sync.aligned.m16n8k16.row.col.f32.f16.f16.f32 "
      "{%0,%1,%2,%3}, {%4,%5,%6,%7}, {%8,%9}, {%0,%1,%2,%3};"
      : "+f"(d[0]), "+f"(d[1]), "+f"(d[2]), "+f"(d[3])
      : "r"(a[0]), "r"(a[1]), "r"(a[2]), "r"(a[3]), "r"(b[0]), "r"(b[1]));
}

__global__ void __launch_bounds__(256, 3)
gemm_mma(int a1id, int nk1, int nk2, int bid, int nkB,
         const float* __restrict__ bias, int cid) {
  const int tid = threadIdx.x;
  const int wid = tid >> 5;
  const int lane = tid & 31;
  const int warpM = wid & 1;
  const int warpN = wid >> 1;
  const int rowTile = blockIdx.x * 64;
  const int colTile = blockIdx.y * 128;

  const uint4* __restrict__ A1 = (a1id == 1) ? gP1 : gP2;
  const uint4* __restrict__ A2 = gP2;
  const uint2* __restrict__ Bf =
      (bid == 1) ? gB1 : (bid == 2) ? gBsk : (bid == 3) ? gB2 : gB3;

  int mtile[2];
#pragma unroll
  for (int mt = 0; mt < 2; ++mt) mtile[mt] = blockIdx.x * 4 + warpM * 2 + mt;

  const uint2* bBase = Bf + ((size_t)(blockIdx.y * 16 + warpN * 4) * nkB) * 32 + lane;

  float acc[2][4][4];
#pragma unroll
  for (int mt = 0; mt < 2; ++mt)
#pragma unroll
    for (int nt = 0; nt < 4; ++nt)
#pragma unroll
      for (int r = 0; r < 4; ++r) acc[mt][nt][r] = 0.f;

  const int nks = nk1 + nk2;

  uint4 aB[2][2];
  uint2 bB[2][4];
  auto ldA = [&](int ks, int buf) {
#pragma unroll
    for (int mt = 0; mt < 2; ++mt) {
      if (ks < nk1) aB[buf][mt] = A1[((size_t)mtile[mt] * nk1 + ks) * 32 + lane];
      else          aB[buf][mt] = A2[((size_t)mtile[mt] * nk2 + (ks - nk1)) * 32 + lane];
    }
  };
  auto ldB = [&](int ks, int buf) {
#pragma unroll
    for (int nt = 0; nt < 4; ++nt) bB[buf][nt] = bBase[(size_t)nt * nkB * 32 + ks * 32];
  };

  ldA(0, 0);
  ldB(0, 0);
#pragma unroll 2
  for (int ks = 0; ks < nks; ++ks) {
    const int buf = ks & 1;
    if (ks + 1 < nks) { ldA(ks + 1, buf ^ 1); ldB(ks + 1, buf ^ 1); }
#pragma unroll
    for (int mt = 0; mt < 2; ++mt)
#pragma unroll
      for (int nt = 0; nt < 4; ++nt)
        mma_f16(acc[mt][nt], (const uint32_t*)&aB[buf][mt],
                (const uint32_t*)&bB[buf][nt]);
  }

  __half* __restrict__ C = (cid == 1) ? gThalf : gShalf;
  const int r0base = rowTile + warpM * 32 + (lane >> 2);
  const int cbase = colTile + warpN * 32 + (lane & 3) * 2;
#pragma unroll
  for (int mt = 0; mt < 2; ++mt) {
    const int rr = r0base + mt * 16;
#pragma unroll
    for (int nt = 0; nt < 4; ++nt) {
      const int col = cbase + nt * 8;
      float2 bv = make_float2(0.f, 0.f);
      if (bias) bv = *(const float2*)(bias + col);
      if (rr < NN)
        *(__half2*)(C + (size_t)rr * 256 + col) =
            __floats2half2_rn(acc[mt][nt][0] + bv.x, acc[mt][nt][1] + bv.y);
      if (rr + 8 < NN)
        *(__half2*)(C + (size_t)(rr + 8) * 256 + col) =
            __floats2half2_rn(acc[mt][nt][2] + bv.x, acc[mt][nt][3] + bv.y);
    }
  }
}

// ===================== LayerNorm + ReLU + skip (mtile CTA) =================
// T read fp16 (gThalf). layer==1: skip=gShalf; writes gHhalf + gP2 frags.
// layer==2: skip=gHhalf; writes gP2 frags only.
__global__ void __launch_bounds__(512)
ln_kernel(const float* __restrict__ gamma, const float* __restrict__ beta,
          int layer) {
  __shared__ uint32_t sf[2048];
  const int mtile = blockIdx.x;
  const int wid = threadIdx.x >> 5, lane = threadIdx.x & 31;
  const int row = mtile * 16 + wid;
  const uint2* t2 = (const uint2*)gThalf + (size_t)row * 64;
  float4 v0 = unpack_u2(t2[lane]);
  float4 v1 = unpack_u2(t2[lane + 32]);
  float sum = v0.x + v0.y + v0.z + v0.w + v1.x + v1.y + v1.z + v1.w;
  float sq = v0.x * v0.x + v0.y * v0.y + v0.z * v0.z + v0.w * v0.w +
             v1.x * v1.x + v1.y * v1.y + v1.z * v1.z + v1.w * v1.w;
#pragma unroll
  for (int off = 16; off > 0; off >>= 1) {
    sum += __shfl_xor_sync(0xffffffffu, sum, off);
    sq  += __shfl_xor_sync(0xffffffffu, sq, off);
  }
  const float mu = sum * (1.0f / DH);
  const float var = sq * (1.0f / DH) - mu * mu;
  const float rs = rsqrtf(var + 1e-5f);

  const uint2* s2 = (const uint2*)((layer == 1) ? gShalf : gHhalf) +
                    (size_t)row * 64;
  float4 sv0 = unpack_u2(s2[lane]);
  float4 sv1 = unpack_u2(s2[lane + 32]);

  const float4* g4 = (const float4*)gamma;
  const float4* b4 = (const float4*)beta;
#pragma unroll
  for (int v = 0; v < 2; ++v) {
    float4 tv = (v == 0) ? v0 : v1;
    float4 sv = (v == 0) ? sv0 : sv1;
    float4 gv = g4[lane + 32 * v];
    float4 bv = b4[lane + 32 * v];
    float4 r;
    r.x = fmaxf(0.f, (tv.x - mu) * rs * gv.x + bv.x) + sv.x;
    r.y = fmaxf(0.f, (tv.y - mu) * rs * gv.y + bv.y) + sv.y;
    r.z = fmaxf(0.f, (tv.z - mu) * rs * gv.z + bv.z) + sv.z;
    r.w = fmaxf(0.f, (tv.w - mu) * rs * gv.w + bv.w) + sv.w;
    const uint32_t w0 = pack_h2(r.x, r.y);
    const uint32_t w1 = pack_h2(r.z, r.w);
    const int col = lane + 32 * v;
    if (layer == 1)
      ((uint2*)gHhalf)[(size_t)row * 64 + col] = make_uint2(w0, w1);
    smem_afrag(sf, 2 * col, wid, w0);
    smem_afrag(sf, 2 * col + 1, wid, w1);
  }
  __syncthreads();
  uint4* dst = gP2 + (size_t)mtile * 512;     // nk=16: 512 uint4 per mtile
  dst[threadIdx.x] = ((const uint4*)sf)[threadIdx.x];
}

// ===================== launch ==============================================
extern "C" void kernel_launch(void* const* d_in, const int* in_sizes, int n_in,
                              void* d_out, int out_size) {
  const float* x   = (const float*)d_in[0];
  const int*   ei  = (const int*)d_in[1];
  const float* W1l = (const float*)d_in[2];
  const float* b1l = (const float*)d_in[3];
  const float* W1r = (const float*)d_in[4];
  const float* g1  = (const float*)d_in[5];
  const float* be1 = (const float*)d_in[6];
  const float* Wsk = (const float*)d_in[7];
  const float* bsk = (const float*)d_in[8];
  const float* W2l = (const float*)d_in[9];
  const float* b2l = (const float*)d_in[10];
  const float* W2r = (const float*)d_in[11];
  const float* g2  = (const float*)d_in[12];
  const float* be2 = (const float*)d_in[13];
  const float* W3l = (const float*)d_in[14];
  const float* b3l = (const float*)d_in[15];
  const float* W3r = (const float*)d_in[16];
  float* out = (float*)d_out;

  const int* src = ei;
  const int* dst = ei + EE;

  const int edgeBlocks = (EE + 255) / 256;
  const int warpBlocks = (NN + 7) / 8;
  const dim3 gemmGrid((NN + 63) / 64, 2);

  // #1 pack_x(+zero_deg) ; #2 prep ; #3 count ; #4 GEMM (profiled slot)
  pack_x_kernel<<<NTILE, 512>>>(x);
  prep_all<<<(147456 + 255) / 256, 256>>>(W1l, W1r, Wsk, W2l, W2r, W3l, W3r);
  count_kernel<<<edgeBlocks, 256>>>(dst);
  gemm_mma<<<gemmGrid, 256>>>(2, 8, 0, 2, 8, bsk, 2);    // S = x@Wsk + bsk

  scan_kernel<<<1, 1024>>>();
  fill_kernel<<<edgeBlocks, 256>>>(src, dst);

  // ---- layer 1: T = [agg(x)|x] @ [W1l;W1r] + b1l ; H = relu(LN(T)) + S
  agg_x_kernel<<<NTILE, 512>>>();
  gemm_mma<<<gemmGrid, 256>>>(1, 8, 8, 1, 16, b1l, 1);
  ln_kernel<<<NTILE, 512>>>(g1, be1, 1);

  // ---- layer 2: T = [agg(H)|H] @ [W2l;W2r] + b2l ; H2 = relu(LN(T)) + H
  agg_h_kernel<<<NTILE, 512>>>();
  gemm_mma<<<gemmGrid, 256>>>(1, 16, 16, 3, 32, b2l, 1);
  ln_kernel<<<NTILE, 512>>>(g2, be2, 2);

  // ---- layer 3: T = H2 @ [W3l|W3r] (fp16) ;
  //      out = mean_agg(T[:,:128]) + T[:,128:] + b3l
  gemm_mma<<<gemmGrid, 256>>>(2, 16, 0, 4, 16, nullptr, 1);
  agg_final_kernel<<<warpBlocks, 256>>>(b3l, out);
}